// round 14
// baseline (speedup 1.0000x reference)
#include <cuda_runtime.h>
#include <cuda_fp16.h>
#include <cstdint>

// UpSmpl — conv3d(64->256,3x3x3,pad1) + pixel-shuffle x2 + skip,
// via warp-level mma.sync m16n8k16 fp16 (f32 accum) + ldmatrix.
// R14: m32n32 warp tile, 3 CTAs/SM (reg cap 85), A-ring2 + B-ring3.
// x: (1,64,17,128,128) f32   W: (256,64,3,3,3) f32   b: (256,) f32
// out: (1,32,33,256,256) f32

#define ZP 19
#define YP 130
#define XPD 130
#define ICN 64
#define NTAP 27
#define NOC 256

__device__ __align__(256) __half g_xTh[(size_t)ZP * YP * XPD * ICN]; // padded, [z][y][x][ic]
__device__ __align__(256) __half g_Wth[(size_t)NTAP * NOC * ICN];    // [tap][oc][ic]

#define ABUF (130 * 72)        // halves: 130 rows x 144B
#define BBUF (64 * 72)         // halves: 64 oc rows x 144B
#define SMEM_BYTES ((2 * ABUF + 3 * BBUF) * 2)   // 65088 B

// ---------------- PTX helpers ----------------
__device__ __forceinline__ uint32_t smem_u32(const void* p) {
    uint32_t a;
    asm("{ .reg .u64 t; cvta.to.shared.u64 t, %1; cvt.u32.u64 %0, t; }" : "=r"(a) : "l"(p));
    return a;
}
__device__ __forceinline__ void cpa16(uint32_t dst, const void* src) {
    asm volatile("cp.async.cg.shared.global [%0], [%1], 16;" :: "r"(dst), "l"(src));
}
#define CP_COMMIT() asm volatile("cp.async.commit_group;")
#define CP_WAIT1()  asm volatile("cp.async.wait_group 1;" ::: "memory")

__device__ __forceinline__ void mma16(float* d, const uint32_t* a, const uint32_t* b) {
    asm volatile(
        "mma.sync.aligned.m16n8k16.row.col.f32.f16.f16.f32 "
        "{%0,%1,%2,%3}, {%4,%5,%6,%7}, {%8,%9}, {%0,%1,%2,%3};"
        : "+f"(d[0]), "+f"(d[1]), "+f"(d[2]), "+f"(d[3])
        : "r"(a[0]), "r"(a[1]), "r"(a[2]), "r"(a[3]), "r"(b[0]), "r"(b[1]));
}
__device__ __forceinline__ void ldsm4(uint32_t& r0, uint32_t& r1, uint32_t& r2,
                                      uint32_t& r3, uint32_t addr) {
    asm volatile("ldmatrix.sync.aligned.m8n8.x4.shared.b16 {%0,%1,%2,%3}, [%4];"
                 : "=r"(r0), "=r"(r1), "=r"(r2), "=r"(r3) : "r"(addr));
}

// ---------------- prep kernels ----------------
#define HALO_ZF (2 * YP * XPD)
#define HALO_YS (17 * 2 * XPD)
#define HALO_XS (17 * 128 * 2)
#define HALO_CELLS (HALO_ZF + HALO_YS + HALO_XS)

__global__ void zero_halo_kernel() {
    int i = blockIdx.x * blockDim.x + threadIdx.x;
    if (i >= HALO_CELLS) return;
    int zz, yy, xx;
    if (i < HALO_ZF) {
        int f = i / (YP * XPD), r = i % (YP * XPD);
        zz = f * (ZP - 1); yy = r / XPD; xx = r % XPD;
    } else if (i < HALO_ZF + HALO_YS) {
        int j = i - HALO_ZF;
        int zi = j / (2 * XPD), r = j % (2 * XPD);
        zz = 1 + zi; yy = (r / XPD) * (YP - 1); xx = r % XPD;
    } else {
        int j = i - HALO_ZF - HALO_YS;
        int zi = j / (128 * 2), r = j % (128 * 2);
        zz = 1 + zi; yy = 1 + r / 2; xx = (r & 1) * (XPD - 1);
    }
    uint4* p = (uint4*)(g_xTh + (((size_t)zz * YP + yy) * XPD + xx) * ICN);
    #pragma unroll
    for (int k = 0; k < 8; ++k) p[k] = make_uint4(0, 0, 0, 0);
}

__global__ void prep_x_kernel(const float* __restrict__ xin) {
    __shared__ unsigned short ts[64 * 129];
    const int tid = threadIdx.x;
    const int z = blockIdx.y, y = blockIdx.x;
    for (int i = tid; i < 2048; i += 256) {
        int ic = i >> 5, xq = i & 31;
        float4 v = ((const float4*)xin)[(((size_t)ic * 17 + z) * 128 + y) * 32 + xq];
        ts[ic * 129 + xq * 4 + 0] = __half_as_ushort(__float2half_rn(v.x));
        ts[ic * 129 + xq * 4 + 1] = __half_as_ushort(__float2half_rn(v.y));
        ts[ic * 129 + xq * 4 + 2] = __half_as_ushort(__float2half_rn(v.z));
        ts[ic * 129 + xq * 4 + 3] = __half_as_ushort(__float2half_rn(v.w));
    }
    __syncthreads();
    size_t obase = (((size_t)(z + 1) * YP + (y + 1)) * XPD + 1) * ICN;
    for (int i = tid; i < 2048; i += 256) {
        int xx = i >> 4, icq = i & 15;
        uint2 w;
        w.x = (uint32_t)ts[(icq * 4 + 0) * 129 + xx]
            | ((uint32_t)ts[(icq * 4 + 1) * 129 + xx] << 16);
        w.y = (uint32_t)ts[(icq * 4 + 2) * 129 + xx]
            | ((uint32_t)ts[(icq * 4 + 3) * 129 + xx] << 16);
        *(uint2*)(g_xTh + obase + (size_t)xx * ICN + icq * 4) = w;
    }
}

__global__ void prep_w_kernel(const float* __restrict__ win) {
    const int oc = blockIdx.x;
    for (int i = threadIdx.x; i < 64 * 27; i += 256) {
        int ic = i / 27, tap = i % 27;
        g_Wth[((size_t)tap * NOC + oc) * ICN + ic] =
            __float2half_rn(win[(size_t)oc * 1728 + i]);
    }
}

// ---------------- main MMA kernel ----------------
// CTA: M=128 pixels x N=64 oc, 256 thr = 8 warps (4M x 2N), warp tile m32n32.
// 27 K-stages = 9 slabs x 3 kx; A ring-2, B ring-3 (buf == kx, static).
__global__ void __launch_bounds__(256, 3)
upsmpl_mma_kernel(const float* __restrict__ xin, const float* __restrict__ bin,
                  float* __restrict__ outp)
{
    extern __shared__ __half smh[];
    const int tid  = threadIdx.x;
    const int lane = tid & 31, wid = tid >> 5;
    const int g = lane >> 2, tig = lane & 3;
    const int wm = wid & 3, wn = wid >> 2;

    const int y  = blockIdx.x;          // 0..127
    const int z  = blockIdx.y;          // 0..16
    const int ocbase = blockIdx.z * 64; // 0..3 -> 64-oc group

    const uint32_t sA = smem_u32(smh);
    const uint32_t sB = sA + 2u * ABUF * 2u;

    // ldmatrix lane address pieces (byte units)
    const int lrow  = ((lane >> 3) & 1) * 8 + (lane & 7);
    const int lcolB = (lane >> 4) * 16;
    const uint32_t aLaneOff = (uint32_t)((wm * 32 + lrow) * 144 + lcolB);
    const uint32_t bLaneOff = (uint32_t)((wn * 32 + lrow) * 144 + lcolB);

    // Hoisted cp.async per-thread offset tables.
    uint32_t bDst[2], aDst[5];
    uint32_t bSrc[2], aSrc[5];
    #pragma unroll
    for (int k = 0; k < 2; ++k) {       // B: 64 rows x 8 chunks = 512
        int i = tid + 256 * k, r = i >> 3, c = i & 7;
        bDst[k] = (uint32_t)(r * 144 + c * 16);
        bSrc[k] = (uint32_t)(r * ICN * 2 + c * 16);
    }
    #pragma unroll
    for (int k = 0; k < 5; ++k) {       // A: 130 rows x 8 chunks = 1040
        int i = tid + 256 * k, r = i >> 3, c = i & 7;
        aDst[k] = (uint32_t)(r * 144 + c * 16);
        aSrc[k] = (uint32_t)(r * ICN * 2 + c * 16);
    }
    const char* wbase = (const char*)(g_Wth + (size_t)ocbase * ICN);
    const char* xbase = (const char*)(g_xTh + (size_t)z * YP * XPD * ICN
                                            + (size_t)y * XPD * ICN);

    auto loadA = [&](int s, uint32_t buf) {   // slab s = kz*3+ky (0..8)
        const int kz = s / 3, ky = s - kz * 3;
        const char* src = xbase + ((size_t)kz * YP + ky) * XPD * ICN * 2;
        const uint32_t dst = sA + buf * (ABUF * 2u);
        #pragma unroll
        for (int k = 0; k < 4; ++k) cpa16(dst + aDst[k], src + aSrc[k]);
        if (tid < 16) cpa16(dst + aDst[4], src + aSrc[4]);
    };
    auto loadB = [&](int tap, uint32_t buf) {
        const char* src = wbase + (size_t)tap * (NOC * ICN * 2);
        const uint32_t dst = sB + buf * (BBUF * 2u);
        #pragma unroll
        for (int k = 0; k < 2; ++k) cpa16(dst + bDst[k], src + bSrc[k]);
    };

    float d[2][4][4];                   // [mf][f][reg]  m32 x n32
    #pragma unroll
    for (int mf = 0; mf < 2; ++mf)
        #pragma unroll
        for (int f = 0; f < 4; ++f)
            #pragma unroll
            for (int r = 0; r < 4; ++r) d[mf][f][r] = 0.f;

    loadA(0, 0); loadB(0, 0); CP_COMMIT();
    loadB(1, 1); CP_COMMIT();           // stage 1 uses slab 0 (kx=1)

    #pragma unroll 1
    for (int jo = 0; jo < 9; ++jo) {    // slab index; stage = 3*jo + kx
        const uint32_t Ab = sA + (uint32_t)(jo & 1) * (ABUF * 2u);
        #pragma unroll
        for (int kx = 0; kx < 3; ++kx) {
            CP_WAIT1();
            __syncthreads();   // publishes stage data; fences prior-stage reads
                               // so loads below may overwrite recycled buffers.

            const uint32_t aBase = Ab + aLaneOff + (uint32_t)(kx * 144);
            const uint32_t bBase = sB + (uint32_t)kx * (BBUF * 2u) + bLaneOff;

            #pragma unroll
            for (int c = 0; c < 4; ++c) {      // k16 chunks, per-warp skew
                const int cs = (c + wid) & 3;
                uint32_t a[2][4], b[4][2];
                #pragma unroll
                for (int mf = 0; mf < 2; ++mf)
                    ldsm4(a[mf][0], a[mf][1], a[mf][2], a[mf][3],
                          aBase + (uint32_t)(mf * 16 * 144 + cs * 32));
                ldsm4(b[0][0], b[1][0], b[0][1], b[1][1],
                      bBase + (uint32_t)(cs * 32));
                ldsm4(b[2][0], b[3][0], b[2][1], b[3][1],
                      bBase + (uint32_t)(16 * 144 + cs * 32));

                if (c == 0) {
                    // Issue stage+2 prefetch inside chunk-0's ldsm->mma shadow.
                    const int stage = 3 * jo + kx;
                    if (stage + 2 < 27) loadB(stage + 2, (uint32_t)((kx + 2) % 3));
                    if (kx == 0 && jo + 1 < 9) loadA(jo + 1, (uint32_t)((jo + 1) & 1));
                    CP_COMMIT();         // exactly one group per stage
                }

                #pragma unroll
                for (int mf = 0; mf < 2; ++mf)
                    #pragma unroll
                    for (int f = 0; f < 4; ++f)
                        mma16(d[mf][f], a[mf], b[f]);
            }
        }
    }

    // ---------------- epilogue: bias + shuffle scatter + skip ----------------
    #pragma unroll
    for (int mf = 0; mf < 2; ++mf) {
        #pragma unroll
        for (int rh = 0; rh < 2; ++rh) {
            const int x = wm * 32 + mf * 16 + rh * 8 + g;
            #pragma unroll
            for (int f = 0; f < 4; ++f) {
                #pragma unroll
                for (int par = 0; par < 2; ++par) {
                    const int oc = ocbase + wn * 32 + f * 8 + 2 * tig + par;
                    const float acc = d[mf][f][rh * 2 + par];
                    if (z == 0) {
                        if (oc & 32) continue;
                        const int q = (oc >> 6) & 1, p = oc >> 7, nn = oc & 31;
                        const int sic = (p * 64 + q * 32 + nn) >> 1;
                        const float v = acc + bin[oc]
                                      + xin[(size_t)sic * 17 * 16384 + (size_t)y * 128 + x];
                        outp[((size_t)nn * 33 * 256 + (2 * y + p)) * 256 + 2 * x + q] = v;
                    } else {
                        const int nn = oc & 31, q = (oc >> 5) & 1;
                        const int p = (oc >> 6) & 1, a = oc >> 7;
                        const float v = acc + bin[oc]
                            + xin[((size_t)(oc >> 2) * 17 + z) * 16384 + (size_t)y * 128 + x];
                        const size_t o = (((size_t)nn * 33 + (2 * z - 1 + a)) * 256
                                          + (2 * y + p)) * 256 + 2 * x + q;
                        outp[o] = v;
                    }
                }
            }
        }
    }
}

extern "C" void kernel_launch(void* const* d_in, const int* in_sizes, int n_in,
                              void* d_out, int out_size) {
    const float* x = (const float*)d_in[0];
    const float* W = (const float*)d_in[1];
    const float* b = (const float*)d_in[2];
    float* out = (float*)d_out;

    cudaFuncSetAttribute(upsmpl_mma_kernel,
                         cudaFuncAttributeMaxDynamicSharedMemorySize, SMEM_BYTES);

    zero_halo_kernel<<<(HALO_CELLS + 255) / 256, 256>>>();
    prep_x_kernel<<<dim3(128, 17), 256>>>(x);
    prep_w_kernel<<<256, 256>>>(W);
    upsmpl_mma_kernel<<<dim3(128, 17, 4), 256, SMEM_BYTES>>>(x, b, out);
}

// round 15
// speedup vs baseline: 1.1545x; 1.1545x over previous
#include <cuda_runtime.h>
#include <cuda_fp16.h>
#include <cstdint>

// UpSmpl — conv3d(64->256,3x3x3,pad1) + pixel-shuffle x2 + skip,
// via warp-level mma.sync m16n8k16 fp16 (f32 accum).
// R15: A via cp.async+ldsm (ring-3, 1 barrier/slab); B via fragment-linear
// gmem (LDG.64 straight into mma regs) — no B smem, 9 barriers total.
// x: (1,64,17,128,128) f32   W: (256,64,3,3,3) f32   b: (256,) f32
// out: (1,32,33,256,256) f32

#define ZP 19
#define YP 130
#define XPD 130
#define ICN 64
#define NTAP 27
#define NOC 256

__device__ __align__(256) __half g_xTh[(size_t)ZP * YP * XPD * ICN]; // padded, [z][y][x][ic]
// B fragment-linear: [tap][ob(32)][c(4)][lane(32)] x uint2 {b0,b1}
__device__ __align__(256) uint2 g_Bf[(size_t)NTAP * 32 * 4 * 32];

#define ABUF (130 * 72)        // halves: 130 rows x 144B
#define SMEM_BYTES (3 * ABUF * 2)   // 56160 B (A ring-3 only)

// ---------------- PTX helpers ----------------
__device__ __forceinline__ uint32_t smem_u32(const void* p) {
    uint32_t a;
    asm("{ .reg .u64 t; cvta.to.shared.u64 t, %1; cvt.u32.u64 %0, t; }" : "=r"(a) : "l"(p));
    return a;
}
__device__ __forceinline__ void cpa16(uint32_t dst, const void* src) {
    asm volatile("cp.async.cg.shared.global [%0], [%1], 16;" :: "r"(dst), "l"(src));
}
#define CP_COMMIT() asm volatile("cp.async.commit_group;")
#define CP_WAIT1()  asm volatile("cp.async.wait_group 1;" ::: "memory")

__device__ __forceinline__ void mma16(float* d, const uint32_t* a, uint2 b) {
    asm volatile(
        "mma.sync.aligned.m16n8k16.row.col.f32.f16.f16.f32 "
        "{%0,%1,%2,%3}, {%4,%5,%6,%7}, {%8,%9}, {%0,%1,%2,%3};"
        : "+f"(d[0]), "+f"(d[1]), "+f"(d[2]), "+f"(d[3])
        : "r"(a[0]), "r"(a[1]), "r"(a[2]), "r"(a[3]), "r"(b.x), "r"(b.y));
}
__device__ __forceinline__ void ldsm4(uint32_t& r0, uint32_t& r1, uint32_t& r2,
                                      uint32_t& r3, uint32_t addr) {
    asm volatile("ldmatrix.sync.aligned.m8n8.x4.shared.b16 {%0,%1,%2,%3}, [%4];"
                 : "=r"(r0), "=r"(r1), "=r"(r2), "=r"(r3) : "r"(addr));
}

// ---------------- prep kernels ----------------
#define HALO_ZF (2 * YP * XPD)
#define HALO_YS (17 * 2 * XPD)
#define HALO_XS (17 * 128 * 2)
#define HALO_CELLS (HALO_ZF + HALO_YS + HALO_XS)

__global__ void zero_halo_kernel() {
    int i = blockIdx.x * blockDim.x + threadIdx.x;
    if (i >= HALO_CELLS) return;
    int zz, yy, xx;
    if (i < HALO_ZF) {
        int f = i / (YP * XPD), r = i % (YP * XPD);
        zz = f * (ZP - 1); yy = r / XPD; xx = r % XPD;
    } else if (i < HALO_ZF + HALO_YS) {
        int j = i - HALO_ZF;
        int zi = j / (2 * XPD), r = j % (2 * XPD);
        zz = 1 + zi; yy = (r / XPD) * (YP - 1); xx = r % XPD;
    } else {
        int j = i - HALO_ZF - HALO_YS;
        int zi = j / (128 * 2), r = j % (128 * 2);
        zz = 1 + zi; yy = 1 + r / 2; xx = (r & 1) * (XPD - 1);
    }
    uint4* p = (uint4*)(g_xTh + (((size_t)zz * YP + yy) * XPD + xx) * ICN);
    #pragma unroll
    for (int k = 0; k < 8; ++k) p[k] = make_uint4(0, 0, 0, 0);
}

__global__ void prep_x_kernel(const float* __restrict__ xin) {
    __shared__ unsigned short ts[64 * 129];
    const int tid = threadIdx.x;
    const int z = blockIdx.y, y = blockIdx.x;
    for (int i = tid; i < 2048; i += 256) {
        int ic = i >> 5, xq = i & 31;
        float4 v = ((const float4*)xin)[(((size_t)ic * 17 + z) * 128 + y) * 32 + xq];
        ts[ic * 129 + xq * 4 + 0] = __half_as_ushort(__float2half_rn(v.x));
        ts[ic * 129 + xq * 4 + 1] = __half_as_ushort(__float2half_rn(v.y));
        ts[ic * 129 + xq * 4 + 2] = __half_as_ushort(__float2half_rn(v.z));
        ts[ic * 129 + xq * 4 + 3] = __half_as_ushort(__float2half_rn(v.w));
    }
    __syncthreads();
    size_t obase = (((size_t)(z + 1) * YP + (y + 1)) * XPD + 1) * ICN;
    for (int i = tid; i < 2048; i += 256) {
        int xx = i >> 4, icq = i & 15;
        uint2 w;
        w.x = (uint32_t)ts[(icq * 4 + 0) * 129 + xx]
            | ((uint32_t)ts[(icq * 4 + 1) * 129 + xx] << 16);
        w.y = (uint32_t)ts[(icq * 4 + 2) * 129 + xx]
            | ((uint32_t)ts[(icq * 4 + 3) * 129 + xx] << 16);
        *(uint2*)(g_xTh + obase + (size_t)xx * ICN + icq * 4) = w;
    }
}

// Pack W into fragment-linear B: for (tap, ob, c, lane=g*4+tig):
//   b0 = {W[ob*8+g][c*16 +    tig*2], W[..][+1]}   (k = tig*2, tig*2+1)
//   b1 = {W[ob*8+g][c*16 + 8+ tig*2], W[..][+1]}   (k = 8+tig*2, ..)
__global__ void prep_wfrag_kernel(const float* __restrict__ win) {
    const int tap = blockIdx.x;
    const int tid = threadIdx.x;
    for (int k = 0; k < 16; ++k) {
        int i = tid + k * 256;                 // 0..4095
        int ob = i >> 7, rem = i & 127;
        int c = rem >> 5, lane = rem & 31;
        int g = lane >> 2, tig = lane & 3;
        int oc = ob * 8 + g;
        const float* wr = win + ((size_t)oc * 64) * 27 + tap;  // + ic*27
        int ic0 = c * 16 + tig * 2;
        __half h0 = __float2half_rn(wr[(size_t)ic0 * 27]);
        __half h1 = __float2half_rn(wr[(size_t)(ic0 + 1) * 27]);
        __half h2 = __float2half_rn(wr[(size_t)(ic0 + 8) * 27]);
        __half h3 = __float2half_rn(wr[(size_t)(ic0 + 9) * 27]);
        uint2 v;
        v.x = (uint32_t)__half_as_ushort(h0) | ((uint32_t)__half_as_ushort(h1) << 16);
        v.y = (uint32_t)__half_as_ushort(h2) | ((uint32_t)__half_as_ushort(h3) << 16);
        g_Bf[(((size_t)tap * 32 + ob) * 4 + c) * 32 + lane] = v;
    }
}

// ---------------- main MMA kernel ----------------
// CTA: M=128 pixels x N=128 oc, 256 thr = 8 warps (4M x 2N), warp tile m32n64.
// 9 A-slabs (kz,ky) x 3 kx stages each; ONE barrier per slab. B from g_Bf via
// LDG.64 (chunk double-buffered), A via ldsm from ring-3 smem.
__global__ void __launch_bounds__(256, 2)
upsmpl_mma_kernel(const float* __restrict__ xin, const float* __restrict__ bin,
                  float* __restrict__ outp)
{
    extern __shared__ __half smh[];
    const int tid  = threadIdx.x;
    const int lane = tid & 31, wid = tid >> 5;
    const int g = lane >> 2, tig = lane & 3;
    const int wm = wid & 3, wn = wid >> 2;

    const int y  = blockIdx.x;          // 0..127
    const int z  = blockIdx.y;          // 0..16
    const int ocbase = blockIdx.z * 128;

    const uint32_t sA = smem_u32(smh);

    // ldmatrix lane address pieces (byte units)
    const int lrow  = ((lane >> 3) & 1) * 8 + (lane & 7);
    const int lcolB = (lane >> 4) * 16;
    const uint32_t aLaneOff = (uint32_t)((wm * 32 + lrow) * 144 + lcolB);

    // B fragment pointer for this warp: ob base = ocbase/8 + wn*8
    const uint2* __restrict__ bpWarp =
        g_Bf + ((size_t)(blockIdx.z * 16 + wn * 8) * 4) * 32 + lane;

    // Hoisted cp.async per-thread offset tables (A: 130 rows x 8 chunks).
    uint32_t aDst[5], aSrc[5];
    #pragma unroll
    for (int k = 0; k < 5; ++k) {
        int i = tid + 256 * k, r = i >> 3, c = i & 7;
        aDst[k] = (uint32_t)(r * 144 + c * 16);
        aSrc[k] = (uint32_t)(r * ICN * 2 + c * 16);
    }
    const char* xbase = (const char*)(g_xTh + (size_t)z * YP * XPD * ICN
                                            + (size_t)y * XPD * ICN);

    auto loadA = [&](int s, uint32_t buf) {   // slab s = kz*3+ky (0..8)
        const int kz = s / 3, ky = s - kz * 3;
        const char* src = xbase + ((size_t)kz * YP + ky) * XPD * ICN * 2;
        const uint32_t dst = sA + buf * (ABUF * 2u);
        #pragma unroll
        for (int k = 0; k < 4; ++k) cpa16(dst + aDst[k], src + aSrc[k]);
        if (tid < 16) cpa16(dst + aDst[4], src + aSrc[4]);
    };

    float d[2][8][4];
    #pragma unroll
    for (int mf = 0; mf < 2; ++mf)
        #pragma unroll
        for (int f = 0; f < 8; ++f)
            #pragma unroll
            for (int r = 0; r < 4; ++r) d[mf][f][r] = 0.f;

    loadA(0, 0); CP_COMMIT();
    loadA(1, 1); CP_COMMIT();

    #pragma unroll 1
    for (int jo = 0; jo < 9; ++jo) {    // slab; stages = 3*jo + kx
        CP_WAIT1();
        __syncthreads();                // slab jo resident; prior slab reads done
        if (jo + 2 < 9) loadA(jo + 2, (uint32_t)((jo + 2) % 3));
        CP_COMMIT();                    // one group per slab (may be empty)

        const uint32_t Ab = sA + (uint32_t)(jo % 3) * (ABUF * 2u);
        #pragma unroll
        for (int kx = 0; kx < 3; ++kx) {
            const int tap = 3 * jo + kx;
            const uint32_t aBase = Ab + aLaneOff + (uint32_t)(kx * 144);
            const uint2* __restrict__ bp = bpWarp + (size_t)tap * 4096;

            uint2 bb[2][8];             // B chunk double buffer (LDG.64)
            #pragma unroll
            for (int f = 0; f < 8; ++f) bb[0][f] = bp[f * 128];

            #pragma unroll
            for (int c = 0; c < 4; ++c) {      // k16 chunks
                const int cur = c & 1;
                if (c < 3) {
                    #pragma unroll
                    for (int f = 0; f < 8; ++f)
                        bb[cur ^ 1][f] = bp[f * 128 + (c + 1) * 32];
                }
                uint32_t a[2][4];
                #pragma unroll
                for (int mf = 0; mf < 2; ++mf)
                    ldsm4(a[mf][0], a[mf][1], a[mf][2], a[mf][3],
                          aBase + (uint32_t)(mf * 16 * 144 + c * 32));
                #pragma unroll
                for (int mf = 0; mf < 2; ++mf)
                    #pragma unroll
                    for (int f = 0; f < 8; ++f)
                        mma16(d[mf][f], a[mf], bb[cur][f]);
            }
        }
    }

    // ---------------- epilogue: bias + shuffle scatter + skip ----------------
    #pragma unroll
    for (int mf = 0; mf < 2; ++mf) {
        #pragma unroll
        for (int rh = 0; rh < 2; ++rh) {
            const int x = wm * 32 + mf * 16 + rh * 8 + g;
            if (z == 0) {
                #pragma unroll
                for (int f = 0; f < 4; ++f) {       // f>=4 -> oc&32 -> discarded
                    #pragma unroll
                    for (int par = 0; par < 2; ++par) {
                        const int oc = ocbase + wn * 64 + f * 8 + 2 * tig + par;
                        const int q = (oc >> 6) & 1, p = oc >> 7, nn = oc & 31;
                        const int sic = (p * 64 + q * 32 + nn) >> 1;
                        const float v = d[mf][f][rh * 2 + par] + bin[oc]
                                      + xin[(size_t)sic * 17 * 16384 + (size_t)y * 128 + x];
                        outp[((size_t)nn * 33 * 256 + (2 * y + p)) * 256 + 2 * x + q] = v;
                    }
                }
            } else {
                #pragma unroll
                for (int f = 0; f < 4; ++f) {
                    #pragma unroll
                    for (int par = 0; par < 2; ++par) {
                        const int oc0 = ocbase + wn * 64 + f * 8 + 2 * tig + par;
                        const int oc1 = oc0 + 32;   // q=1 partner
                        const float v0 = d[mf][f][rh * 2 + par] + bin[oc0]
                            + xin[((size_t)(oc0 >> 2) * 17 + z) * 16384 + (size_t)y * 128 + x];
                        const float v1 = d[mf][f + 4][rh * 2 + par] + bin[oc1]
                            + xin[((size_t)(oc1 >> 2) * 17 + z) * 16384 + (size_t)y * 128 + x];
                        const int nn = oc0 & 31, p = (oc0 >> 6) & 1, a = oc0 >> 7;
                        const size_t o = (((size_t)nn * 33 + (2 * z - 1 + a)) * 256
                                          + (2 * y + p)) * 256 + 2 * x;
                        *(float2*)(outp + o) = make_float2(v0, v1);
                    }
                }
            }
        }
    }
}

extern "C" void kernel_launch(void* const* d_in, const int* in_sizes, int n_in,
                              void* d_out, int out_size) {
    const float* x = (const float*)d_in[0];
    const float* W = (const float*)d_in[1];
    const float* b = (const float*)d_in[2];
    float* out = (float*)d_out;

    cudaFuncSetAttribute(upsmpl_mma_kernel,
                         cudaFuncAttributeMaxDynamicSharedMemorySize, SMEM_BYTES);

    zero_halo_kernel<<<(HALO_CELLS + 255) / 256, 256>>>();
    prep_x_kernel<<<dim3(128, 17), 256>>>(x);
    prep_wfrag_kernel<<<27, 256>>>(W);
    upsmpl_mma_kernel<<<dim3(128, 17, 2), 256, SMEM_BYTES>>>(x, b, out);
}

// round 16
// speedup vs baseline: 1.2208x; 1.0574x over previous
#include <cuda_runtime.h>
#include <cuda_fp16.h>
#include <cstdint>

// UpSmpl — conv3d(64->256,3x3x3,pad1) + pixel-shuffle x2 + skip,
// via warp-level mma.sync m16n8k16 fp16 (f32 accum).
// R16: B fragment-linear gmem with CONTINUOUS cross-tap prefetch pipeline
// (uniform +1024 chunk stride, parity static); A via cp.async+ldsm ring-3,
// 1 barrier/slab (9 total); epilogue skip-load CSE.
// x: (1,64,17,128,128) f32   W: (256,64,3,3,3) f32   b: (256,) f32
// out: (1,32,33,256,256) f32

#define ZP 19
#define YP 130
#define XPD 130
#define ICN 64
#define NTAP 27
#define NOC 256

__device__ __align__(256) __half g_xTh[(size_t)ZP * YP * XPD * ICN]; // padded, [z][y][x][ic]
// B fragment-linear: [tap][c(4)][ob(32)][lane(32)] x uint2 {b0,b1} + 1 pad chunk
__device__ __align__(256) uint2 g_Bf[(size_t)NTAP * 4 * 32 * 32 + 1024];

#define ABUF (130 * 72)        // halves: 130 rows x 144B
#define SMEM_BYTES (3 * ABUF * 2)   // 56160 B (A ring-3 only)

// ---------------- PTX helpers ----------------
__device__ __forceinline__ uint32_t smem_u32(const void* p) {
    uint32_t a;
    asm("{ .reg .u64 t; cvta.to.shared.u64 t, %1; cvt.u32.u64 %0, t; }" : "=r"(a) : "l"(p));
    return a;
}
__device__ __forceinline__ void cpa16(uint32_t dst, const void* src) {
    asm volatile("cp.async.cg.shared.global [%0], [%1], 16;" :: "r"(dst), "l"(src));
}
#define CP_COMMIT() asm volatile("cp.async.commit_group;")
#define CP_WAIT1()  asm volatile("cp.async.wait_group 1;" ::: "memory")

__device__ __forceinline__ void mma16(float* d, const uint32_t* a, uint2 b) {
    asm volatile(
        "mma.sync.aligned.m16n8k16.row.col.f32.f16.f16.f32 "
        "{%0,%1,%2,%3}, {%4,%5,%6,%7}, {%8,%9}, {%0,%1,%2,%3};"
        : "+f"(d[0]), "+f"(d[1]), "+f"(d[2]), "+f"(d[3])
        : "r"(a[0]), "r"(a[1]), "r"(a[2]), "r"(a[3]), "r"(b.x), "r"(b.y));
}
__device__ __forceinline__ void ldsm4(uint32_t& r0, uint32_t& r1, uint32_t& r2,
                                      uint32_t& r3, uint32_t addr) {
    asm volatile("ldmatrix.sync.aligned.m8n8.x4.shared.b16 {%0,%1,%2,%3}, [%4];"
                 : "=r"(r0), "=r"(r1), "=r"(r2), "=r"(r3) : "r"(addr));
}

// ---------------- prep kernels ----------------
#define HALO_ZF (2 * YP * XPD)
#define HALO_YS (17 * 2 * XPD)
#define HALO_XS (17 * 128 * 2)
#define HALO_CELLS (HALO_ZF + HALO_YS + HALO_XS)

__global__ void zero_halo_kernel() {
    int i = blockIdx.x * blockDim.x + threadIdx.x;
    if (i >= HALO_CELLS) return;
    int zz, yy, xx;
    if (i < HALO_ZF) {
        int f = i / (YP * XPD), r = i % (YP * XPD);
        zz = f * (ZP - 1); yy = r / XPD; xx = r % XPD;
    } else if (i < HALO_ZF + HALO_YS) {
        int j = i - HALO_ZF;
        int zi = j / (2 * XPD), r = j % (2 * XPD);
        zz = 1 + zi; yy = (r / XPD) * (YP - 1); xx = r % XPD;
    } else {
        int j = i - HALO_ZF - HALO_YS;
        int zi = j / (128 * 2), r = j % (128 * 2);
        zz = 1 + zi; yy = 1 + r / 2; xx = (r & 1) * (XPD - 1);
    }
    uint4* p = (uint4*)(g_xTh + (((size_t)zz * YP + yy) * XPD + xx) * ICN);
    #pragma unroll
    for (int k = 0; k < 8; ++k) p[k] = make_uint4(0, 0, 0, 0);
}

__global__ void prep_x_kernel(const float* __restrict__ xin) {
    __shared__ unsigned short ts[64 * 129];
    const int tid = threadIdx.x;
    const int z = blockIdx.y, y = blockIdx.x;
    for (int i = tid; i < 2048; i += 256) {
        int ic = i >> 5, xq = i & 31;
        float4 v = ((const float4*)xin)[(((size_t)ic * 17 + z) * 128 + y) * 32 + xq];
        ts[ic * 129 + xq * 4 + 0] = __half_as_ushort(__float2half_rn(v.x));
        ts[ic * 129 + xq * 4 + 1] = __half_as_ushort(__float2half_rn(v.y));
        ts[ic * 129 + xq * 4 + 2] = __half_as_ushort(__float2half_rn(v.z));
        ts[ic * 129 + xq * 4 + 3] = __half_as_ushort(__float2half_rn(v.w));
    }
    __syncthreads();
    size_t obase = (((size_t)(z + 1) * YP + (y + 1)) * XPD + 1) * ICN;
    for (int i = tid; i < 2048; i += 256) {
        int xx = i >> 4, icq = i & 15;
        uint2 w;
        w.x = (uint32_t)ts[(icq * 4 + 0) * 129 + xx]
            | ((uint32_t)ts[(icq * 4 + 1) * 129 + xx] << 16);
        w.y = (uint32_t)ts[(icq * 4 + 2) * 129 + xx]
            | ((uint32_t)ts[(icq * 4 + 3) * 129 + xx] << 16);
        *(uint2*)(g_xTh + obase + (size_t)xx * ICN + icq * 4) = w;
    }
}

// Pack W into fragment-linear B, layout [tap][c][ob][lane]:
//   lane = g*4+tig, ob = oc/8 (g = oc%8):
//   b0 = {W[ob*8+g][c*16 +    tig*2], W[..][+1]}
//   b1 = {W[ob*8+g][c*16 + 8+ tig*2], W[..][+1]}
__global__ void prep_wfrag_kernel(const float* __restrict__ win) {
    const int tap = blockIdx.x;
    const int tid = threadIdx.x;
    for (int k = 0; k < 16; ++k) {
        int i = tid + k * 256;                 // 0..4095
        int ob = i >> 7, rem = i & 127;
        int c = rem >> 5, lane = rem & 31;
        int g = lane >> 2, tig = lane & 3;
        int oc = ob * 8 + g;
        const float* wr = win + ((size_t)oc * 64) * 27 + tap;  // + ic*27
        int ic0 = c * 16 + tig * 2;
        __half h0 = __float2half_rn(wr[(size_t)ic0 * 27]);
        __half h1 = __float2half_rn(wr[(size_t)(ic0 + 1) * 27]);
        __half h2 = __float2half_rn(wr[(size_t)(ic0 + 8) * 27]);
        __half h3 = __float2half_rn(wr[(size_t)(ic0 + 9) * 27]);
        uint2 v;
        v.x = (uint32_t)__half_as_ushort(h0) | ((uint32_t)__half_as_ushort(h1) << 16);
        v.y = (uint32_t)__half_as_ushort(h2) | ((uint32_t)__half_as_ushort(h3) << 16);
        g_Bf[(((size_t)tap * 4 + c) * 32 + ob) * 32 + lane] = v;
    }
}

// ---------------- main MMA kernel ----------------
// CTA: M=128 pixels x N=128 oc, 256 thr = 8 warps (4M x 2N), warp tile m32n64.
// 9 A-slabs (kz,ky) x 3 kx taps x 4 k16 chunks; 1 barrier per slab.
// B prefetched one chunk ahead, continuously across tap/slab boundaries.
__global__ void __launch_bounds__(256, 2)
upsmpl_mma_kernel(const float* __restrict__ xin, const float* __restrict__ bin,
                  float* __restrict__ outp)
{
    extern __shared__ __half smh[];
    const int tid  = threadIdx.x;
    const int lane = tid & 31, wid = tid >> 5;
    const int g = lane >> 2, tig = lane & 3;
    const int wm = wid & 3, wn = wid >> 2;

    const int y  = blockIdx.x;          // 0..127
    const int z  = blockIdx.y;          // 0..16
    const int ocbase = blockIdx.z * 128;

    const uint32_t sA = smem_u32(smh);

    // ldmatrix lane address pieces (byte units)
    const int lrow  = ((lane >> 3) & 1) * 8 + (lane & 7);
    const int lcolB = (lane >> 4) * 16;
    const uint32_t aLaneOff = (uint32_t)((wm * 32 + lrow) * 144 + lcolB);

    // B fragment base for this warp: + f*32 per frag, +1024 per chunk (uniform)
    const uint2* __restrict__ bq =
        g_Bf + (size_t)(blockIdx.z * 16 + wn * 8) * 32 + lane;

    // Hoisted cp.async per-thread offset tables (A: 130 rows x 8 chunks).
    uint32_t aDst[5], aSrc[5];
    #pragma unroll
    for (int k = 0; k < 5; ++k) {
        int i = tid + 256 * k, r = i >> 3, c = i & 7;
        aDst[k] = (uint32_t)(r * 144 + c * 16);
        aSrc[k] = (uint32_t)(r * ICN * 2 + c * 16);
    }
    const char* xbase = (const char*)(g_xTh + (size_t)z * YP * XPD * ICN
                                            + (size_t)y * XPD * ICN);

    auto loadA = [&](int s, uint32_t buf) {   // slab s = kz*3+ky (0..8)
        const int kz = s / 3, ky = s - kz * 3;
        const char* src = xbase + ((size_t)kz * YP + ky) * XPD * ICN * 2;
        const uint32_t dst = sA + buf * (ABUF * 2u);
        #pragma unroll
        for (int k = 0; k < 4; ++k) cpa16(dst + aDst[k], src + aSrc[k]);
        if (tid < 16) cpa16(dst + aDst[4], src + aSrc[4]);
    };

    float d[2][8][4];
    #pragma unroll
    for (int mf = 0; mf < 2; ++mf)
        #pragma unroll
        for (int f = 0; f < 8; ++f)
            #pragma unroll
            for (int r = 0; r < 4; ++r) d[mf][f][r] = 0.f;

    loadA(0, 0); CP_COMMIT();
    loadA(1, 1); CP_COMMIT();

    // Prime B pipeline: chunk q=0 into bb[0].
    uint2 bb[2][8];
    #pragma unroll
    for (int f = 0; f < 8; ++f) bb[0][f] = bq[f * 32];
    const uint2* __restrict__ bt = bq;        // current tap base (advances +4096)

    #pragma unroll 1
    for (int jo = 0; jo < 9; ++jo) {    // slab; taps = 3*jo + kx
        CP_WAIT1();
        __syncthreads();                // slab jo resident; prior slab reads done
        if (jo + 2 < 9) loadA(jo + 2, (uint32_t)((jo + 2) % 3));
        CP_COMMIT();                    // one group per slab (may be empty)

        const uint32_t Ab = sA + (uint32_t)(jo % 3) * (ABUF * 2u);
        #pragma unroll
        for (int kx = 0; kx < 3; ++kx) {
            const uint32_t aBase = Ab + aLaneOff + (uint32_t)(kx * 144);

            #pragma unroll
            for (int c = 0; c < 4; ++c) {      // k16 chunks; parity static (c&1)
                // prefetch next global chunk (crosses tap/slab; pad absorbs end)
                #pragma unroll
                for (int f = 0; f < 8; ++f)
                    bb[(c + 1) & 1][f] = bt[(c + 1) * 1024 + f * 32];

                uint32_t a[2][4];
                #pragma unroll
                for (int mf = 0; mf < 2; ++mf)
                    ldsm4(a[mf][0], a[mf][1], a[mf][2], a[mf][3],
                          aBase + (uint32_t)(mf * 16 * 144 + c * 32));
                #pragma unroll
                for (int mf = 0; mf < 2; ++mf)
                    #pragma unroll
                    for (int f = 0; f < 8; ++f)
                        mma16(d[mf][f], a[mf], bb[c & 1][f]);
            }
            bt += 4096;                 // next tap
        }
    }

    // ---------------- epilogue: bias + shuffle scatter + skip ----------------
    #pragma unroll
    for (int mf = 0; mf < 2; ++mf) {
        #pragma unroll
        for (int rh = 0; rh < 2; ++rh) {
            const int x = wm * 32 + mf * 16 + rh * 8 + g;
            if (z == 0) {
                #pragma unroll
                for (int f = 0; f < 4; ++f) {       // f>=4 -> oc&32 -> discarded
                    const int oce = ocbase + wn * 64 + f * 8 + 2 * tig;
                    const int q = (oce >> 6) & 1, p = oce >> 7;
                    const int sic = (p * 64 + q * 32 + (oce & 31)) >> 1; // par-inv
                    const float s = xin[(size_t)sic * 17 * 16384 + (size_t)y * 128 + x];
                    #pragma unroll
                    for (int par = 0; par < 2; ++par) {
                        const int oc = oce + par;
                        const float v = d[mf][f][rh * 2 + par] + bin[oc] + s;
                        outp[((size_t)(oc & 31) * 33 * 256 + (2 * y + p)) * 256
                             + 2 * x + q] = v;
                    }
                }
            } else {
                #pragma unroll
                for (int f = 0; f < 4; ++f) {
                    const int oce = ocbase + wn * 64 + f * 8 + 2 * tig;   // par=0
                    const float s0 = xin[((size_t)(oce >> 2) * 17 + z) * 16384
                                         + (size_t)y * 128 + x];
                    const float s1 = xin[((size_t)((oce + 32) >> 2) * 17 + z) * 16384
                                         + (size_t)y * 128 + x];
                    #pragma unroll
                    for (int par = 0; par < 2; ++par) {
                        const int oc0 = oce + par, oc1 = oc0 + 32;
                        const float v0 = d[mf][f][rh * 2 + par] + bin[oc0] + s0;
                        const float v1 = d[mf][f + 4][rh * 2 + par] + bin[oc1] + s1;
                        const int nn = oc0 & 31, p = (oc0 >> 6) & 1, a = oc0 >> 7;
                        const size_t o = (((size_t)nn * 33 + (2 * z - 1 + a)) * 256
                                          + (2 * y + p)) * 256 + 2 * x;
                        *(float2*)(outp + o) = make_float2(v0, v1);
                    }
                }
            }
        }
    }
}

extern "C" void kernel_launch(void* const* d_in, const int* in_sizes, int n_in,
                              void* d_out, int out_size) {
    const float* x = (const float*)d_in[0];
    const float* W = (const float*)d_in[1];
    const float* b = (const float*)d_in[2];
    float* out = (float*)d_out;

    cudaFuncSetAttribute(upsmpl_mma_kernel,
                         cudaFuncAttributeMaxDynamicSharedMemorySize, SMEM_BYTES);

    zero_halo_kernel<<<(HALO_CELLS + 255) / 256, 256>>>();
    prep_x_kernel<<<dim3(128, 17), 256>>>(x);
    prep_wfrag_kernel<<<27, 256>>>(W);
    upsmpl_mma_kernel<<<dim3(128, 17, 2), 256, SMEM_BYTES>>>(x, b, out);
}